// round 14
// baseline (speedup 1.0000x reference)
#include <cuda_runtime.h>
#include <cuda_bf16.h>
#include <cstdint>

#define IN_FEAT   256
#define OUT_FEAT  32
#define MAXN      102400
#define CAP       64             // bucket slots per row (avg degree 16)
#define MAXOVF    8192
#define TM        256
#define NT        256
#define KCH       16             // k-floats per staged chunk (64 B per row)
#define NCHUNK    (IN_FEAT / KCH)   // 16
#define SFP       20             // padded floats per staged row
#define KP        260
#define SWT_ELEMS (OUT_FEAT * KP)
#define SF_ELEMS  (TM * SFP)
#define SMEM_BYTES ((SWT_ELEMS + 2 * SF_ELEMS) * 4)   // 72.5 KB -> 3 blocks/SM

__device__ float g_x[MAXN * OUT_FEAT];          // projected features (13 MB)
__device__ int   g_cnt[MAXN];
__device__ uint2 g_bucket[(size_t)MAXN * CAP];  // (col, val_bits) (52 MB)
__device__ int   g_ovf_n;
__device__ int   g_ovf[MAXOVF];

// ---------------------------------------------------------------------------
// helpers
// ---------------------------------------------------------------------------
__device__ __forceinline__ unsigned smem_u32(const void* p) {
    return (unsigned)__cvta_generic_to_shared(p);
}
__device__ __forceinline__ void cp_async16(unsigned dst, const void* src) {
    asm volatile("cp.async.cg.shared.global [%0], [%1], 16;"
                 :: "r"(dst), "l"(src));
}
__device__ __forceinline__ void cp_commit() {
    asm volatile("cp.async.commit_group;");
}
template <int N>
__device__ __forceinline__ void cp_wait() {
    asm volatile("cp.async.wait_group %0;" :: "n"(N));
}
__device__ __forceinline__ unsigned f2tf32(float f) {
    unsigned r;
    asm("cvt.rna.tf32.f32 %0, %1;" : "=r"(r) : "f"(f));
    return r;
}
__device__ __forceinline__ void mma_tf32(float& c0, float& c1, float& c2, float& c3,
                                         unsigned a0, unsigned a1, unsigned a2, unsigned a3,
                                         unsigned b0, unsigned b1) {
    asm volatile("mma.sync.aligned.m16n8k8.row.col.f32.tf32.tf32.f32 "
                 "{%0,%1,%2,%3}, {%4,%5,%6,%7}, {%8,%9}, {%0,%1,%2,%3};"
                 : "+f"(c0), "+f"(c1), "+f"(c2), "+f"(c3)
                 : "r"(a0), "r"(a1), "r"(a2), "r"(a3), "r"(b0), "r"(b1));
}

// ---------------------------------------------------------------------------
// Stage 1: x = feat @ W   (TF32 MMA)
// 72.5 KB smem + reg cap 85 (launch_bounds 256,3) -> 3 blocks/SM -> all
// 391 blocks resident in ONE wave (was 1.32 waves with 32% idle tail).
// ---------------------------------------------------------------------------
__global__ __launch_bounds__(NT, 3)
void gemm_kernel(const float* __restrict__ feat,
                 const float* __restrict__ weight,
                 int n_nodes) {
    extern __shared__ char smem[];
    unsigned* sWt = (unsigned*)smem;
    float*    sF  = (float*)(smem + SWT_ELEMS * 4);

    const int t    = threadIdx.x;
    const int warp = t >> 5;
    const int lane = t & 31;
    const int gid  = lane >> 2;
    const int tid4 = lane & 3;
    const int row0 = blockIdx.x * TM;

    // stage chunk c (KCH=16 floats per row): TM*4 16B segments
    auto stage = [&](int c, int b) {
        #pragma unroll
        for (int i = 0; i < (TM * 4) / NT; i++) {
            int idx = i * NT + t;
            int r   = idx >> 2;
            int s   = idx & 3;
            int gr  = row0 + r;
            if (gr > n_nodes - 1) gr = n_nodes - 1;
            const float* src = feat + (size_t)gr * IN_FEAT + c * KCH + s * 4;
            cp_async16(smem_u32(&sF[b * SF_ELEMS + r * SFP + s * 4]), src);
        }
        cp_commit();
    };

    stage(0, 0);

    #pragma unroll
    for (int i = 0; i < (IN_FEAT * OUT_FEAT) / NT; i++) {
        int idx = i * NT + t;
        int k = idx >> 5;
        int n = idx & 31;
        sWt[n * KP + k] = f2tf32(weight[idx]);
    }

    float acc[2][4][4];
    #pragma unroll
    for (int m = 0; m < 2; m++)
        #pragma unroll
        for (int n = 0; n < 4; n++)
            #pragma unroll
            for (int i = 0; i < 4; i++) acc[m][n][i] = 0.f;

    #pragma unroll 1
    for (int c = 0; c < NCHUNK; c++) {
        int b = c & 1;
        if (c + 1 < NCHUNK) { stage(c + 1, b ^ 1); cp_wait<1>(); }
        else                { cp_wait<0>(); }
        __syncthreads();

        const float* fb = &sF[b * SF_ELEMS];
        #pragma unroll
        for (int ks = 0; ks < KCH / 8; ks++) {
            int kl = ks * 8;
            int kg = c * KCH + kl;

            unsigned bf[4][2];
            #pragma unroll
            for (int n = 0; n < 4; n++) {
                const unsigned* wp = &sWt[(n * 8 + gid) * KP + kg + tid4];
                bf[n][0] = wp[0];
                bf[n][1] = wp[4];
            }

            unsigned af[2][4];
            #pragma unroll
            for (int m = 0; m < 2; m++) {
                int rb = warp * 32 + m * 16 + gid;
                const float* ap0 = &fb[rb * SFP + kl + tid4];
                const float* ap1 = &fb[(rb + 8) * SFP + kl + tid4];
                af[m][0] = f2tf32(ap0[0]);
                af[m][1] = f2tf32(ap1[0]);
                af[m][2] = f2tf32(ap0[4]);
                af[m][3] = f2tf32(ap1[4]);
            }

            #pragma unroll
            for (int n = 0; n < 4; n++)
                #pragma unroll
                for (int m = 0; m < 2; m++)
                    mma_tf32(acc[m][n][0], acc[m][n][1], acc[m][n][2], acc[m][n][3],
                             af[m][0], af[m][1], af[m][2], af[m][3],
                             bf[n][0], bf[n][1]);
        }
        __syncthreads();
    }

    #pragma unroll
    for (int m = 0; m < 2; m++) {
        int r0 = row0 + warp * 32 + m * 16 + gid;
        #pragma unroll
        for (int n = 0; n < 4; n++) {
            int col = n * 8 + 2 * tid4;
            if (r0 < n_nodes) {
                float2 v = make_float2(acc[m][n][0], acc[m][n][1]);
                *(float2*)(g_x + (size_t)r0 * OUT_FEAT + col) = v;
            }
            if (r0 + 8 < n_nodes) {
                float2 v = make_float2(acc[m][n][2], acc[m][n][3]);
                *(float2*)(g_x + (size_t)(r0 + 8) * OUT_FEAT + col) = v;
            }
        }
    }
}

// ---------------------------------------------------------------------------
__global__ void zero_kernel(int n) {
    int i = blockIdx.x * 256 + threadIdx.x;
    if (i < n) g_cnt[i] = 0;
    if (i == 0) g_ovf_n = 0;
}

// ---------------------------------------------------------------------------
// bucketize: 4 consecutive edges/thread, vectorized (R13, measured best)
// ---------------------------------------------------------------------------
__global__ __launch_bounds__(256)
void scatter_kernel(const float* __restrict__ vals,
                    const int* __restrict__ erow,
                    const int* __restrict__ ecol,
                    int n_edges) {
    int idx = blockIdx.x * 256 + threadIdx.x;
    int e = idx * 4;
    if (e + 3 < n_edges) {
        int4   r4 = *(const int4*)(erow + e);
        int4   c4 = *(const int4*)(ecol + e);
        float4 v4 = *(const float4*)(vals + e);
        int r[4] = {r4.x, r4.y, r4.z, r4.w};
        int c[4] = {c4.x, c4.y, c4.z, c4.w};
        float v[4] = {v4.x, v4.y, v4.z, v4.w};
        int pos[4];
        #pragma unroll
        for (int i = 0; i < 4; i++)
            pos[i] = atomicAdd(&g_cnt[r[i]], 1);
        #pragma unroll
        for (int i = 0; i < 4; i++) {
            if (pos[i] < CAP) {
                g_bucket[(size_t)r[i] * CAP + pos[i]] =
                    make_uint2((unsigned)c[i], __float_as_uint(v[i]));
            } else {
                int o = atomicAdd(&g_ovf_n, 1);
                if (o < MAXOVF) g_ovf[o] = e + i;
            }
        }
    } else {
        for (int i = 0; i < 4; i++) {
            int ee = e + i;
            if (ee >= n_edges) break;
            int r = __ldg(erow + ee);
            int c = __ldg(ecol + ee);
            float v = __ldg(vals + ee);
            int pos = atomicAdd(&g_cnt[r], 1);
            if (pos < CAP) {
                g_bucket[(size_t)r * CAP + pos] =
                    make_uint2((unsigned)c, __float_as_uint(v));
            } else {
                int o = atomicAdd(&g_ovf_n, 1);
                if (o < MAXOVF) g_ovf[o] = ee;
            }
        }
    }
}

// ---------------------------------------------------------------------------
// gather: R13-exact (8 thr/row, 4 cols, 8-edge batches, uint4 pair loads)
// ---------------------------------------------------------------------------
__global__ __launch_bounds__(256)
void gather_kernel(float* __restrict__ out, int n_nodes) {
    int idx = blockIdx.x * 256 + threadIdx.x;
    int row = idx >> 3;
    if (row >= n_nodes) return;
    int q = (idx & 7) << 2;

    int cnt = g_cnt[row];
    if (cnt > CAP) cnt = CAP;
    const uint2* bk = g_bucket + (size_t)row * CAP;
    const uint4* bk4 = (const uint4*)bk;

    float4 acc; acc.x = acc.y = acc.z = acc.w = 0.f;

    int j = 0;
    for (; j + 8 <= cnt; j += 8) {
        uint4 pp[4];
        #pragma unroll
        for (int u = 0; u < 4; u++) pp[u] = bk4[(j >> 1) + u];
        float4 xv[8];
        #pragma unroll
        for (int u = 0; u < 4; u++) {
            xv[2*u]   = *(const float4*)(g_x + (size_t)pp[u].x * OUT_FEAT + q);
            xv[2*u+1] = *(const float4*)(g_x + (size_t)pp[u].z * OUT_FEAT + q);
        }
        #pragma unroll
        for (int u = 0; u < 4; u++) {
            float v0 = __uint_as_float(pp[u].y);
            float v1 = __uint_as_float(pp[u].w);
            acc.x += v0 * xv[2*u].x + v1 * xv[2*u+1].x;
            acc.y += v0 * xv[2*u].y + v1 * xv[2*u+1].y;
            acc.z += v0 * xv[2*u].z + v1 * xv[2*u+1].z;
            acc.w += v0 * xv[2*u].w + v1 * xv[2*u+1].w;
        }
    }
    if (j + 4 <= cnt) {
        uint4 pp[2];
        #pragma unroll
        for (int u = 0; u < 2; u++) pp[u] = bk4[(j >> 1) + u];
        float4 xv[4];
        #pragma unroll
        for (int u = 0; u < 2; u++) {
            xv[2*u]   = *(const float4*)(g_x + (size_t)pp[u].x * OUT_FEAT + q);
            xv[2*u+1] = *(const float4*)(g_x + (size_t)pp[u].z * OUT_FEAT + q);
        }
        #pragma unroll
        for (int u = 0; u < 2; u++) {
            float v0 = __uint_as_float(pp[u].y);
            float v1 = __uint_as_float(pp[u].w);
            acc.x += v0 * xv[2*u].x + v1 * xv[2*u+1].x;
            acc.y += v0 * xv[2*u].y + v1 * xv[2*u+1].y;
            acc.z += v0 * xv[2*u].z + v1 * xv[2*u+1].z;
            acc.w += v0 * xv[2*u].w + v1 * xv[2*u+1].w;
        }
        j += 4;
    }
    for (; j < cnt; j++) {
        uint2 p = bk[j];
        float4 xv = *(const float4*)(g_x + (size_t)p.x * OUT_FEAT + q);
        float v = __uint_as_float(p.y);
        acc.x += v * xv.x; acc.y += v * xv.y;
        acc.z += v * xv.z; acc.w += v * xv.w;
    }

    *(float4*)(out + (size_t)row * OUT_FEAT + q) = acc;
}

// ---------------------------------------------------------------------------
// overflow fixup (expected empty at CAP=64)
// ---------------------------------------------------------------------------
__global__ void fixup_kernel(const float* __restrict__ vals,
                             const int* __restrict__ erow,
                             const int* __restrict__ ecol,
                             float* __restrict__ out) {
    int n = g_ovf_n;
    if (n > MAXOVF) n = MAXOVF;
    int gidx = blockIdx.x * 256 + threadIdx.x;
    for (int i = gidx; i < n * 8; i += gridDim.x * 256) {
        int e = g_ovf[i >> 3];
        int q = (i & 7) << 2;
        int r = erow[e], c = ecol[e];
        float v = vals[e];
        #pragma unroll
        for (int k = 0; k < 4; k++)
            atomicAdd(&out[(size_t)r * OUT_FEAT + q + k],
                      v * g_x[(size_t)c * OUT_FEAT + q + k]);
    }
}

// ---------------------------------------------------------------------------
extern "C" void kernel_launch(void* const* d_in, const int* in_sizes, int n_in,
                              void* d_out, int out_size) {
    const float* feat   = (const float*)d_in[0];
    const float* weight = (const float*)d_in[1];
    const float* vals   = (const float*)d_in[2];
    const int*   erow   = (const int*)d_in[3];
    const int*   ecol   = (const int*)d_in[4];
    float* out = (float*)d_out;

    int n_nodes = in_sizes[0] / IN_FEAT;
    int n_edges = in_sizes[2];

    cudaFuncSetAttribute(gemm_kernel,
                         cudaFuncAttributeMaxDynamicSharedMemorySize, SMEM_BYTES);

    int nb_nodes    = (n_nodes + 255) / 256;
    int nb_scat     = (n_edges + 1023) / 1024;
    int gemm_blocks = (n_nodes + TM - 1) / TM;

    zero_kernel<<<nb_nodes, 256>>>(n_nodes);
    scatter_kernel<<<nb_scat, 256>>>(vals, erow, ecol, n_edges);
    gemm_kernel<<<gemm_blocks, NT, SMEM_BYTES>>>(feat, weight, n_nodes);

    long long gw = (long long)n_nodes * 8;
    int nb_gather = (int)((gw + 255) / 256);
    gather_kernel<<<nb_gather, 256>>>(out, n_nodes);

    fixup_kernel<<<32, 256>>>(vals, erow, ecol, out);
}

// round 15
// speedup vs baseline: 1.0217x; 1.0217x over previous
#include <cuda_runtime.h>
#include <cuda.h>
#include <cuda_bf16.h>
#include <cstdint>

#define IN_FEAT   256
#define OUT_FEAT  32
#define MAXN      102400
#define CAP       64             // bucket slots per row (avg degree 16)
#define MAXOVF    8192
#define TM        256
#define NT        256
#define KCH       32             // k-floats per TMA chunk (128 B per row)
#define NCHUNK    (IN_FEAT / KCH)   // 8
#define KP        260
#define SWT_ELEMS (OUT_FEAT * KP)
#define SF_BYTES  (TM * KCH * 4)           // 32768 per buffer
#define SWT_OFF   (2 * SF_BYTES)           // 65536
#define MBAR_OFF  (SWT_OFF + SWT_ELEMS * 4) // 98816
#define SMEM_BYTES (MBAR_OFF + 16)

__device__ float g_x[MAXN * OUT_FEAT];          // projected features (13 MB)
__device__ int   g_cnt[MAXN];
__device__ uint2 g_bucket[(size_t)MAXN * CAP];  // (col, val_bits) (52 MB)
__device__ int   g_ovf_n;
__device__ int   g_ovf[MAXOVF];

// ---------------------------------------------------------------------------
// helpers
// ---------------------------------------------------------------------------
__device__ __forceinline__ unsigned smem_u32(const void* p) {
    return (unsigned)__cvta_generic_to_shared(p);
}
__device__ __forceinline__ unsigned f2tf32(float f) {
    unsigned r;
    asm("cvt.rna.tf32.f32 %0, %1;" : "=r"(r) : "f"(f));
    return r;
}
__device__ __forceinline__ void mma_tf32(float& c0, float& c1, float& c2, float& c3,
                                         unsigned a0, unsigned a1, unsigned a2, unsigned a3,
                                         unsigned b0, unsigned b1) {
    asm volatile("mma.sync.aligned.m16n8k8.row.col.f32.tf32.tf32.f32 "
                 "{%0,%1,%2,%3}, {%4,%5,%6,%7}, {%8,%9}, {%0,%1,%2,%3};"
                 : "+f"(c0), "+f"(c1), "+f"(c2), "+f"(c3)
                 : "r"(a0), "r"(a1), "r"(a2), "r"(a3), "r"(b0), "r"(b1));
}
__device__ __forceinline__ void mbar_init(unsigned a, unsigned cnt) {
    asm volatile("mbarrier.init.shared.b64 [%0], %1;" :: "r"(a), "r"(cnt) : "memory");
}
__device__ __forceinline__ void mbar_expect_tx(unsigned a, unsigned bytes) {
    asm volatile("mbarrier.arrive.expect_tx.shared.b64 _, [%0], %1;"
                 :: "r"(a), "r"(bytes) : "memory");
}
__device__ __forceinline__ void mbar_wait(unsigned a, unsigned parity) {
    unsigned done;
    asm volatile(
        "{\n\t.reg .pred p;\n\t"
        "mbarrier.try_wait.parity.acquire.cta.shared::cta.b64 p, [%1], %2;\n\t"
        "selp.b32 %0, 1, 0, p;\n\t}"
        : "=r"(done) : "r"(a), "r"(parity) : "memory");
    if (!done) {
        asm volatile(
            "{\n\t.reg .pred P1;\n\t"
            "WAIT_LOOP_%=:\n\t"
            "mbarrier.try_wait.parity.acquire.cta.shared::cta.b64 P1, [%0], %1, 0x989680;\n\t"
            "@P1 bra.uni WAIT_DONE_%=;\n\t"
            "bra.uni WAIT_LOOP_%=;\n\t"
            "WAIT_DONE_%=:\n\t}"
            :: "r"(a), "r"(parity) : "memory");
    }
}
__device__ __forceinline__ void tma_load_2d(unsigned dst, const void* map,
                                            int cx, int cy, unsigned mbar) {
    asm volatile(
        "cp.async.bulk.tensor.2d.shared::cta.global.tile.mbarrier::complete_tx::bytes "
        "[%0], [%1, {%2, %3}], [%4];"
        :: "r"(dst), "l"(map), "r"(cx), "r"(cy), "r"(mbar) : "memory");
}

// ---------------------------------------------------------------------------
// Stage 1: x = feat @ W   (TF32 MMA; feat staged by TMA, SW128 swizzle,
// double-buffered with mbarrier parity. Removes the 6.55M cp.async issue
// cost that bound the previous gemm.)
// ---------------------------------------------------------------------------
__global__ __launch_bounds__(NT)
void gemm_kernel(const __grid_constant__ CUtensorMap tmap,
                 const float* __restrict__ weight,
                 int n_nodes) {
    extern __shared__ __align__(1024) char smem[];
    unsigned* sWt = (unsigned*)(smem + SWT_OFF);
    const unsigned smem_base = smem_u32(smem);
    const unsigned mb0 = smem_base + MBAR_OFF;
    const unsigned mb1 = smem_base + MBAR_OFF + 8;

    const int t    = threadIdx.x;
    const int warp = t >> 5;
    const int lane = t & 31;
    const int gid  = lane >> 2;
    const int tid4 = lane & 3;
    const int row0 = blockIdx.x * TM;

    if (t == 0) { mbar_init(mb0, 1); mbar_init(mb1, 1); }
    __syncthreads();

    if (t == 0) {
        mbar_expect_tx(mb0, SF_BYTES);
        tma_load_2d(smem_base, &tmap, 0, row0, mb0);
    }

    // W -> smem (transposed, tf32)
    #pragma unroll
    for (int i = 0; i < (IN_FEAT * OUT_FEAT) / NT; i++) {
        int idx = i * NT + t;
        int k = idx >> 5;
        int n = idx & 31;
        sWt[n * KP + k] = f2tf32(weight[idx]);
    }
    __syncthreads();

    float acc[2][4][4];
    #pragma unroll
    for (int m = 0; m < 2; m++)
        #pragma unroll
        for (int n = 0; n < 4; n++)
            #pragma unroll
            for (int i = 0; i < 4; i++) acc[m][n][i] = 0.f;

    // per-m-tile constants for swizzled A-fragment addressing
    int rbase[2]; unsigned xm[2];
    #pragma unroll
    for (int m = 0; m < 2; m++) {
        int rb = warp * 32 + m * 16 + gid;
        rbase[m] = rb * 128;
        xm[m] = (unsigned)((rb & 7) << 4);
    }

    int ph0 = 0, ph1 = 0;

    #pragma unroll 1
    for (int c = 0; c < NCHUNK; c++) {
        int b = c & 1;
        if (t == 0 && c + 1 < NCHUNK) {
            unsigned mbn = (b ^ 1) ? mb1 : mb0;
            mbar_expect_tx(mbn, SF_BYTES);
            tma_load_2d(smem_base + (unsigned)(b ^ 1) * SF_BYTES, &tmap,
                        (c + 1) * KCH, row0, mbn);
        }
        // wait for chunk c
        if (b == 0) { mbar_wait(mb0, ph0); ph0 ^= 1; }
        else        { mbar_wait(mb1, ph1); ph1 ^= 1; }
        __syncthreads();

        const char* fbB = smem + (unsigned)b * SF_BYTES;
        #pragma unroll
        for (int ks = 0; ks < KCH / 8; ks++) {
            int kl = ks * 8;
            int kg = c * KCH + kl;

            unsigned bf[4][2];
            #pragma unroll
            for (int n = 0; n < 4; n++) {
                const unsigned* wp = &sWt[(n * 8 + gid) * KP + kg + tid4];
                bf[n][0] = wp[0];
                bf[n][1] = wp[4];
            }

            unsigned af[2][4];
            unsigned k1 = (unsigned)((kl + tid4) * 4);
            unsigned k2 = k1 + 16;
            #pragma unroll
            for (int m = 0; m < 2; m++) {
                const char* p0 = fbB + rbase[m];
                const char* p1 = p0 + 1024;          // +8 rows * 128B
                unsigned o1 = k1 ^ xm[m];
                unsigned o2 = k2 ^ xm[m];
                af[m][0] = f2tf32(*(const float*)(p0 + o1));
                af[m][1] = f2tf32(*(const float*)(p1 + o1));
                af[m][2] = f2tf32(*(const float*)(p0 + o2));
                af[m][3] = f2tf32(*(const float*)(p1 + o2));
            }

            #pragma unroll
            for (int n = 0; n < 4; n++)
                #pragma unroll
                for (int m = 0; m < 2; m++)
                    mma_tf32(acc[m][n][0], acc[m][n][1], acc[m][n][2], acc[m][n][3],
                             af[m][0], af[m][1], af[m][2], af[m][3],
                             bf[n][0], bf[n][1]);
        }
        __syncthreads();   // all reads of buffer b done before its next TMA write
    }

    #pragma unroll
    for (int m = 0; m < 2; m++) {
        int r0 = row0 + warp * 32 + m * 16 + gid;
        #pragma unroll
        for (int n = 0; n < 4; n++) {
            int col = n * 8 + 2 * tid4;
            if (r0 < n_nodes) {
                float2 v = make_float2(acc[m][n][0], acc[m][n][1]);
                *(float2*)(g_x + (size_t)r0 * OUT_FEAT + col) = v;
            }
            if (r0 + 8 < n_nodes) {
                float2 v = make_float2(acc[m][n][2], acc[m][n][3]);
                *(float2*)(g_x + (size_t)(r0 + 8) * OUT_FEAT + col) = v;
            }
        }
    }
}

// ---------------------------------------------------------------------------
__global__ void zero_kernel(int n) {
    int i = blockIdx.x * 256 + threadIdx.x;
    if (i < n) g_cnt[i] = 0;
    if (i == 0) g_ovf_n = 0;
}

// ---------------------------------------------------------------------------
// bucketize: 4 consecutive edges/thread, vectorized (R13, measured best)
// ---------------------------------------------------------------------------
__global__ __launch_bounds__(256)
void scatter_kernel(const float* __restrict__ vals,
                    const int* __restrict__ erow,
                    const int* __restrict__ ecol,
                    int n_edges) {
    int idx = blockIdx.x * 256 + threadIdx.x;
    int e = idx * 4;
    if (e + 3 < n_edges) {
        int4   r4 = *(const int4*)(erow + e);
        int4   c4 = *(const int4*)(ecol + e);
        float4 v4 = *(const float4*)(vals + e);
        int r[4] = {r4.x, r4.y, r4.z, r4.w};
        int c[4] = {c4.x, c4.y, c4.z, c4.w};
        float v[4] = {v4.x, v4.y, v4.z, v4.w};
        int pos[4];
        #pragma unroll
        for (int i = 0; i < 4; i++)
            pos[i] = atomicAdd(&g_cnt[r[i]], 1);
        #pragma unroll
        for (int i = 0; i < 4; i++) {
            if (pos[i] < CAP) {
                g_bucket[(size_t)r[i] * CAP + pos[i]] =
                    make_uint2((unsigned)c[i], __float_as_uint(v[i]));
            } else {
                int o = atomicAdd(&g_ovf_n, 1);
                if (o < MAXOVF) g_ovf[o] = e + i;
            }
        }
    } else {
        for (int i = 0; i < 4; i++) {
            int ee = e + i;
            if (ee >= n_edges) break;
            int r = __ldg(erow + ee);
            int c = __ldg(ecol + ee);
            float v = __ldg(vals + ee);
            int pos = atomicAdd(&g_cnt[r], 1);
            if (pos < CAP) {
                g_bucket[(size_t)r * CAP + pos] =
                    make_uint2((unsigned)c, __float_as_uint(v));
            } else {
                int o = atomicAdd(&g_ovf_n, 1);
                if (o < MAXOVF) g_ovf[o] = ee;
            }
        }
    }
}

// ---------------------------------------------------------------------------
// gather: R13-exact (8 thr/row, 4 cols, 8-edge batches, uint4 pair loads)
// ---------------------------------------------------------------------------
__global__ __launch_bounds__(256)
void gather_kernel(float* __restrict__ out, int n_nodes) {
    int idx = blockIdx.x * 256 + threadIdx.x;
    int row = idx >> 3;
    if (row >= n_nodes) return;
    int q = (idx & 7) << 2;

    int cnt = g_cnt[row];
    if (cnt > CAP) cnt = CAP;
    const uint2* bk = g_bucket + (size_t)row * CAP;
    const uint4* bk4 = (const uint4*)bk;

    float4 acc; acc.x = acc.y = acc.z = acc.w = 0.f;

    int j = 0;
    for (; j + 8 <= cnt; j += 8) {
        uint4 pp[4];
        #pragma unroll
        for (int u = 0; u < 4; u++) pp[u] = bk4[(j >> 1) + u];
        float4 xv[8];
        #pragma unroll
        for (int u = 0; u < 4; u++) {
            xv[2*u]   = *(const float4*)(g_x + (size_t)pp[u].x * OUT_FEAT + q);
            xv[2*u+1] = *(const float4*)(g_x + (size_t)pp[u].z * OUT_FEAT + q);
        }
        #pragma unroll
        for (int u = 0; u < 4; u++) {
            float v0 = __uint_as_float(pp[u].y);
            float v1 = __uint_as_float(pp[u].w);
            acc.x += v0 * xv[2*u].x + v1 * xv[2*u+1].x;
            acc.y += v0 * xv[2*u].y + v1 * xv[2*u+1].y;
            acc.z += v0 * xv[2*u].z + v1 * xv[2*u+1].z;
            acc.w += v0 * xv[2*u].w + v1 * xv[2*u+1].w;
        }
    }
    if (j + 4 <= cnt) {
        uint4 pp[2];
        #pragma unroll
        for (int u = 0; u < 2; u++) pp[u] = bk4[(j >> 1) + u];
        float4 xv[4];
        #pragma unroll
        for (int u = 0; u < 2; u++) {
            xv[2*u]   = *(const float4*)(g_x + (size_t)pp[u].x * OUT_FEAT + q);
            xv[2*u+1] = *(const float4*)(g_x + (size_t)pp[u].z * OUT_FEAT + q);
        }
        #pragma unroll
        for (int u = 0; u < 2; u++) {
            float v0 = __uint_as_float(pp[u].y);
            float v1 = __uint_as_float(pp[u].w);
            acc.x += v0 * xv[2*u].x + v1 * xv[2*u+1].x;
            acc.y += v0 * xv[2*u].y + v1 * xv[2*u+1].y;
            acc.z += v0 * xv[2*u].z + v1 * xv[2*u+1].z;
            acc.w += v0 * xv[2*u].w + v1 * xv[2*u+1].w;
        }
        j += 4;
    }
    for (; j < cnt; j++) {
        uint2 p = bk[j];
        float4 xv = *(const float4*)(g_x + (size_t)p.x * OUT_FEAT + q);
        float v = __uint_as_float(p.y);
        acc.x += v * xv.x; acc.y += v * xv.y;
        acc.z += v * xv.z; acc.w += v * xv.w;
    }

    *(float4*)(out + (size_t)row * OUT_FEAT + q) = acc;
}

// ---------------------------------------------------------------------------
// overflow fixup (expected empty at CAP=64)
// ---------------------------------------------------------------------------
__global__ void fixup_kernel(const float* __restrict__ vals,
                             const int* __restrict__ erow,
                             const int* __restrict__ ecol,
                             float* __restrict__ out) {
    int n = g_ovf_n;
    if (n > MAXOVF) n = MAXOVF;
    int gidx = blockIdx.x * 256 + threadIdx.x;
    for (int i = gidx; i < n * 8; i += gridDim.x * 256) {
        int e = g_ovf[i >> 3];
        int q = (i & 7) << 2;
        int r = erow[e], c = ecol[e];
        float v = vals[e];
        #pragma unroll
        for (int k = 0; k < 4; k++)
            atomicAdd(&out[(size_t)r * OUT_FEAT + q + k],
                      v * g_x[(size_t)c * OUT_FEAT + q + k]);
    }
}

// ---------------------------------------------------------------------------
typedef CUresult (*PFN_tmapenc)(
    CUtensorMap*, CUtensorMapDataType, cuuint32_t, void*,
    const cuuint64_t*, const cuuint64_t*, const cuuint32_t*, const cuuint32_t*,
    CUtensorMapInterleave, CUtensorMapSwizzle, CUtensorMapL2promotion,
    CUtensorMapFloatOOBfill);

extern "C" void kernel_launch(void* const* d_in, const int* in_sizes, int n_in,
                              void* d_out, int out_size) {
    const float* feat   = (const float*)d_in[0];
    const float* weight = (const float*)d_in[1];
    const float* vals   = (const float*)d_in[2];
    const int*   erow   = (const int*)d_in[3];
    const int*   ecol   = (const int*)d_in[4];
    float* out = (float*)d_out;

    int n_nodes = in_sizes[0] / IN_FEAT;
    int n_edges = in_sizes[2];

    // driver entry point via cudart (no -lcuda link dependency)
    static PFN_tmapenc encode = nullptr;
    if (!encode) {
        void* p = nullptr;
        cudaDriverEntryPointQueryResult st;
        cudaGetDriverEntryPoint("cuTensorMapEncodeTiled", &p,
                                cudaEnableDefault, &st);
        encode = (PFN_tmapenc)p;
    }

    CUtensorMap tmap;
    {
        cuuint64_t gdim[2] = {(cuuint64_t)IN_FEAT, (cuuint64_t)n_nodes};
        cuuint64_t gstr[1] = {(cuuint64_t)IN_FEAT * 4};
        cuuint32_t box[2]  = {(cuuint32_t)KCH, (cuuint32_t)TM};
        cuuint32_t est[2]  = {1, 1};
        encode(&tmap, CU_TENSOR_MAP_DATA_TYPE_FLOAT32, 2, (void*)feat,
               gdim, gstr, box, est,
               CU_TENSOR_MAP_INTERLEAVE_NONE, CU_TENSOR_MAP_SWIZZLE_128B,
               CU_TENSOR_MAP_L2_PROMOTION_L2_128B,
               CU_TENSOR_MAP_FLOAT_OOB_FILL_NONE);
    }

    cudaFuncSetAttribute(gemm_kernel,
                         cudaFuncAttributeMaxDynamicSharedMemorySize, SMEM_BYTES);

    int nb_nodes    = (n_nodes + 255) / 256;
    int nb_scat     = (n_edges + 1023) / 1024;
    int gemm_blocks = (n_nodes + TM - 1) / TM;

    zero_kernel<<<nb_nodes, 256>>>(n_nodes);
    scatter_kernel<<<nb_scat, 256>>>(vals, erow, ecol, n_edges);
    gemm_kernel<<<gemm_blocks, NT, SMEM_BYTES>>>(tmap, weight, n_nodes);

    long long gw = (long long)n_nodes * 8;
    int nb_gather = (int)((gw + 255) / 256);
    gather_kernel<<<nb_gather, 256>>>(out, n_nodes);

    fixup_kernel<<<32, 256>>>(vals, erow, ecol, out);
}